// round 8
// baseline (speedup 1.0000x reference)
#include <cuda_runtime.h>
#include <cuda_fp8.h>
#include <cstdint>
#include <math.h>

#define NROWS 8192
#define DDIM  64
#define NSTRIP 256                 // 32-row strips
#define NPAIRS2 16512              // sum over si of (128 - si/2)
#define MSE_BLOCKS 512
#define LUT_BLOCKS ((NPAIRS2 + 255) / 256)   // 65
#define THRESH (-20.0f)
#define PAIR_GRID (NPAIRS2 / 8)    // 2064 CTAs x 8 warps

// ---------------- scratch (__device__ globals; no allocations allowed) ----
// fp8 e4m3, K-permuted so one LDG.128 per lane = one mma fragment pair
__device__ __align__(16) uint8_t g_E8[NROWS][DDIM];   // 512 KB
__device__ float g_h[NROWS];             // -0.5 * ||x_i||^2 (fp8-derived)
__device__ float g_rowsum[NROWS];
__device__ float g_msep[MSE_BLOCKS];
__device__ int   g_pair[NPAIRS2];        // (si<<8)|tj
__device__ unsigned int g_ctr;           // zero-init; self-resetting

// fp8 e4m3 MMA m16n8k32, C = 0
__device__ __forceinline__ void mma_zc(float* d, uint32_t a0, uint32_t a1,
                                       uint32_t a2, uint32_t a3,
                                       uint32_t b0, uint32_t b1) {
    asm volatile(
        "mma.sync.aligned.m16n8k32.row.col.f32.e4m3.e4m3.f32 "
        "{%0,%1,%2,%3}, {%4,%5,%6,%7}, {%8,%9}, {%10,%11,%12,%13};"
        : "=f"(d[0]), "=f"(d[1]), "=f"(d[2]), "=f"(d[3])
        : "r"(a0), "r"(a1), "r"(a2), "r"(a3), "r"(b0), "r"(b1),
          "f"(0.0f), "f"(0.0f), "f"(0.0f), "f"(0.0f));
}
// fp8 e4m3 MMA, accumulate
__device__ __forceinline__ void mma_ac(float* d, uint32_t a0, uint32_t a1,
                                       uint32_t a2, uint32_t a3,
                                       uint32_t b0, uint32_t b1) {
    asm volatile(
        "mma.sync.aligned.m16n8k32.row.col.f32.e4m3.e4m3.f32 "
        "{%0,%1,%2,%3}, {%4,%5,%6,%7}, {%8,%9}, {%0,%1,%2,%3};"
        : "+f"(d[0]), "+f"(d[1]), "+f"(d[2]), "+f"(d[3])
        : "r"(a0), "r"(a1), "r"(a2), "r"(a3), "r"(b0), "r"(b1));
}

// cumulative pair count before strip si
__device__ __forceinline__ int pair_base(int s) {
    int a = s >> 1;
    return (s & 1) ? (256 * a + 128 - a * a) : (257 * a - a * a);
}

// ---------------- kernel 1: quantize(+permute) + norms + MSE + LUT --------
__global__ void __launch_bounds__(256) prep_fused(const float* __restrict__ E,
                                                  const float* __restrict__ yt,
                                                  const float* __restrict__ yp) {
    const int bid = blockIdx.x, tid = threadIdx.x;
    if (bid < 32) {
        int i = bid * 256 + tid;
        const float4* row = reinterpret_cast<const float4*>(E + (size_t)i * DDIM);
        uint8_t vb[DDIM];
        float s = 0.0f;
#pragma unroll
        for (int qq = 0; qq < 16; qq++) {
            float4 v = row[qq];
            __nv_fp8_e4m3 a0(v.x), a1(v.y), a2(v.z), a3(v.w);
            float f0 = float(a0), f1 = float(a1), f2 = float(a2), f3 = float(a3);
            s += f0 * f0 + f1 * f1 + f2 * f2 + f3 * f3;
            vb[4 * qq + 0] = a0.__x; vb[4 * qq + 1] = a1.__x;
            vb[4 * qq + 2] = a2.__x; vb[4 * qq + 3] = a3.__x;
        }
        // K-permutation: byte pos p = q*16 + t*4 + b  <-  source k = t*16 + q*4 + b
        uint8_t ob[DDIM];
#pragma unroll
        for (int p = 0; p < DDIM; p++) {
            int q = (p >> 4) & 3, t = (p >> 2) & 3, b = p & 3;
            ob[p] = vb[t * 16 + q * 4 + b];
        }
        uint4* dst = reinterpret_cast<uint4*>(g_E8[i]);
        const uint4* src = reinterpret_cast<const uint4*>(ob);
#pragma unroll
        for (int w = 0; w < 4; w++) dst[w] = src[w];
        g_h[i] = -0.5f * s;
        g_rowsum[i] = 0.0f;
    } else if (bid < 32 + MSE_BLOCKS) {
        __shared__ float sh[8];
        int idx = (bid - 32) * 256 + tid;     // over 131072 float4s
        float4 t = reinterpret_cast<const float4*>(yt)[idx];
        float4 p = reinterpret_cast<const float4*>(yp)[idx];
        float dx = p.x - t.x, dy = p.y - t.y, dz = p.z - t.z, dw = p.w - t.w;
        float s = dx * dx + dy * dy + dz * dz + dw * dw;
#pragma unroll
        for (int o = 16; o > 0; o >>= 1) s += __shfl_down_sync(0xffffffffu, s, o);
        if ((tid & 31) == 0) sh[tid >> 5] = s;
        __syncthreads();
        if (tid < 8) {
            s = sh[tid];
#pragma unroll
            for (int o = 4; o > 0; o >>= 1) s += __shfl_down_sync(0xffu, s, o);
            if (tid == 0) g_msep[bid - 32] = s;
        }
    } else {
        int p = (bid - 32 - MSE_BLOCKS) * 256 + tid;
        if (p < NPAIRS2) {
            float disc = 257.0f * 257.0f - 4.0f * (float)p;
            int a = (int)((257.0f - sqrtf(fmaxf(disc, 0.0f))) * 0.5f);
            int si = 2 * a;
            if (si < 0) si = 0;
            if (si > NSTRIP - 1) si = NSTRIP - 1;
            while (si > 0 && pair_base(si) > p) si--;
            while (si + 1 < NSTRIP && pair_base(si + 1) <= p) si++;
            int tj = (si >> 1) + (p - pair_base(si));
            g_pair[p] = (si << 8) | tj;
        }
    }
}

// ---------------- kernel 2: warp-autonomous 32x64 Gram tiles --------------
__global__ void __launch_bounds__(256) pair_kernel(float* __restrict__ out) {
    __shared__ unsigned int s_last;
    __shared__ float sh_red[256];

    const int tid  = threadIdx.x;
    const int wid  = tid >> 5;
    const int lane = tid & 31;
    const int g    = lane >> 2;        // 0..7
    const int q    = lane & 3;         // 0..3

    const int gid = blockIdx.x * 8 + wid;
    const int pr  = __ldg(&g_pair[gid]);
    const int si  = pr >> 8, tj = pr & 255;
    const int i0  = si * 32, j0 = tj * 64;
    const bool mirror = (tj != (si >> 1));

    // hi for this lane's 4 rows
    float hi[2][2];
#pragma unroll
    for (int mt = 0; mt < 2; mt++) {
        int r0 = i0 + mt * 16 + g;
        hi[mt][0] = __ldg(&g_h[r0]);
        hi[mt][1] = __ldg(&g_h[r0 + 8]);
    }

    // A fragments: 4 coalesced LDG.128 (warp = 8 rows x 64B contiguous)
    uint4 aLo[2], aHi[2];
#pragma unroll
    for (int mt = 0; mt < 2; mt++) {
        aLo[mt] = __ldg(reinterpret_cast<const uint4*>(&g_E8[i0 + mt * 16 + g][q * 16]));
        aHi[mt] = __ldg(reinterpret_cast<const uint4*>(&g_E8[i0 + mt * 16 + g + 8][q * 16]));
    }

    float acc[2][8][4];
    float2 hjv[8];
#pragma unroll
    for (int nt = 0; nt < 8; nt++) {
        uint4 bv = __ldg(reinterpret_cast<const uint4*>(&g_E8[j0 + nt * 8 + g][q * 16]));
        hjv[nt]  = __ldg(reinterpret_cast<const float2*>(&g_h[j0 + nt * 8 + q * 2]));
#pragma unroll
        for (int mt = 0; mt < 2; mt++) {
            mma_zc(acc[mt][nt], aLo[mt].x, aHi[mt].x, aLo[mt].y, aHi[mt].y, bv.x, bv.y);
            mma_ac(acc[mt][nt], aLo[mt].z, aHi[mt].z, aLo[mt].w, aHi[mt].w, bv.z, bv.w);
        }
    }

    // pruning pass: exact args, warp max, no MUFU
    float wmax = -1e30f;
#pragma unroll
    for (int nt = 0; nt < 8; nt++) {
        float hj0 = hjv[nt].x, hj1 = hjv[nt].y;
#pragma unroll
        for (int mt = 0; mt < 2; mt++) {
            float m0 = fmaxf(acc[mt][nt][0] + (hi[mt][0] + hj0),
                             acc[mt][nt][1] + (hi[mt][0] + hj1));
            float m1 = fmaxf(acc[mt][nt][2] + (hi[mt][1] + hj0),
                             acc[mt][nt][3] + (hi[mt][1] + hj1));
            wmax = fmaxf(wmax, fmaxf(m0, m1));
        }
    }

    if (__any_sync(0xffffffffu, wmax > THRESH)) {
        float rs[4] = {0.0f, 0.0f, 0.0f, 0.0f};
#pragma unroll
        for (int nt = 0; nt < 8; nt++) {
            float hj0 = hjv[nt].x, hj1 = hjv[nt].y;
            float c0 = 0.0f, c1 = 0.0f;
#pragma unroll
            for (int mt = 0; mt < 2; mt++) {
                float e0 = __expf(fminf(acc[mt][nt][0] + hi[mt][0] + hj0, 0.0f));
                float e1 = __expf(fminf(acc[mt][nt][1] + hi[mt][0] + hj1, 0.0f));
                float e2 = __expf(fminf(acc[mt][nt][2] + hi[mt][1] + hj0, 0.0f));
                float e3 = __expf(fminf(acc[mt][nt][3] + hi[mt][1] + hj1, 0.0f));
                rs[mt * 2 + 0] += e0 + e1;
                rs[mt * 2 + 1] += e2 + e3;
                c0 += e0 + e2;
                c1 += e1 + e3;
            }
            if (mirror) {
                c0 += __shfl_xor_sync(0xffffffffu, c0, 4);
                c0 += __shfl_xor_sync(0xffffffffu, c0, 8);
                c0 += __shfl_xor_sync(0xffffffffu, c0, 16);
                c1 += __shfl_xor_sync(0xffffffffu, c1, 4);
                c1 += __shfl_xor_sync(0xffffffffu, c1, 8);
                c1 += __shfl_xor_sync(0xffffffffu, c1, 16);
                if (g == nt) {
                    atomicAdd(&g_rowsum[j0 + nt * 8 + q * 2], c0);
                    atomicAdd(&g_rowsum[j0 + nt * 8 + q * 2 + 1], c1);
                }
            }
        }
#pragma unroll
        for (int k = 0; k < 4; k++) {
            rs[k] += __shfl_xor_sync(0xffffffffu, rs[k], 1);
            rs[k] += __shfl_xor_sync(0xffffffffu, rs[k], 2);
        }
        int row = i0 + (q >> 1) * 16 + (q & 1) * 8 + g;
        atomicAdd(&g_rowsum[row], rs[q]);
    }

    // ---- last-CTA final reduction ----
    __threadfence();
    __syncthreads();
    if (tid == 0) {
        unsigned int old = atomicAdd(&g_ctr, 1u);
        s_last = (old == gridDim.x - 1) ? 1u : 0u;
        if (s_last) g_ctr = 0;   // reset for next graph replay
    }
    __syncthreads();
    if (s_last) {
        float s = 0.0f;
        for (int i = tid; i < NROWS; i += 256) s += logf(__ldcg(&g_rowsum[i]));
        float m = 0.0f;
        for (int i = tid; i < MSE_BLOCKS; i += 256) m += g_msep[i];
        sh_red[tid] = s;
        __syncthreads();
        for (int o = 128; o > 0; o >>= 1) {
            if (tid < o) sh_red[tid] += sh_red[tid + o];
            __syncthreads();
        }
        float stot = sh_red[0];
        __syncthreads();
        sh_red[tid] = m;
        __syncthreads();
        for (int o = 128; o > 0; o >>= 1) {
            if (tid < o) sh_red[tid] += sh_red[tid + o];
            __syncthreads();
        }
        if (tid == 0) {
            float kde  = stot / (float)NROWS;
            float IXT  = (logf((float)NROWS) - kde) * 1.44269504088896340736f;
            float dist = sh_red[0] / (float)(NROWS * DDIM);
            out[0] = IXT + 500.0f * dist;
            out[1] = IXT;
            out[2] = dist;
        }
    }
}

extern "C" void kernel_launch(void* const* d_in, const int* in_sizes, int n_in,
                              void* d_out, int out_size) {
    const float* y_true  = (const float*)d_in[0];
    const float* y_pred  = (const float*)d_in[1];
    const float* encoded = (const float*)d_in[2];
    float* out = (float*)d_out;

    prep_fused<<<32 + MSE_BLOCKS + LUT_BLOCKS, 256>>>(encoded, y_true, y_pred);
    pair_kernel<<<PAIR_GRID, 256>>>(out);
}

// round 9
// speedup vs baseline: 1.5161x; 1.5161x over previous
#include <cuda_runtime.h>
#include <cuda_fp8.h>
#include <cstdint>
#include <math.h>

#define NROWS 8192
#define DDIM  64
#define NSTRIP 256                 // 32-row strips
#define NPAIRS2 16512              // sum over si of (128 - si/2)
#define MSE_BLOCKS 512
#define LUT_BLOCKS ((NPAIRS2 + 255) / 256)   // 65
#define THRESH (-20.0f)
#define GRID 304
#define NWARPS (GRID * 8)          // 2432
#define CHUNKW ((NPAIRS2 + NWARPS - 1) / NWARPS)   // 7

// ---------------- scratch (__device__ globals; no allocations allowed) ----
// fp8 e4m3, K-permuted so one LDG.128 per lane = one mma fragment pair
__device__ __align__(16) uint8_t g_E8[NROWS][DDIM];   // 512 KB
__device__ float g_h[NROWS];             // -0.5 * ||x_i||^2 (fp8-derived)
__device__ float g_rowsum[NROWS];
__device__ float g_msep[MSE_BLOCKS];
__device__ int   g_pair[NPAIRS2];        // (si<<8)|tj
__device__ unsigned int g_ctr;           // zero-init; self-resetting

// fp8 e4m3 MMA m16n8k32, C = 0
__device__ __forceinline__ void mma_zc(float* d, uint32_t a0, uint32_t a1,
                                       uint32_t a2, uint32_t a3,
                                       uint32_t b0, uint32_t b1) {
    asm volatile(
        "mma.sync.aligned.m16n8k32.row.col.f32.e4m3.e4m3.f32 "
        "{%0,%1,%2,%3}, {%4,%5,%6,%7}, {%8,%9}, {%10,%11,%12,%13};"
        : "=f"(d[0]), "=f"(d[1]), "=f"(d[2]), "=f"(d[3])
        : "r"(a0), "r"(a1), "r"(a2), "r"(a3), "r"(b0), "r"(b1),
          "f"(0.0f), "f"(0.0f), "f"(0.0f), "f"(0.0f));
}
// fp8 e4m3 MMA, accumulate
__device__ __forceinline__ void mma_ac(float* d, uint32_t a0, uint32_t a1,
                                       uint32_t a2, uint32_t a3,
                                       uint32_t b0, uint32_t b1) {
    asm volatile(
        "mma.sync.aligned.m16n8k32.row.col.f32.e4m3.e4m3.f32 "
        "{%0,%1,%2,%3}, {%4,%5,%6,%7}, {%8,%9}, {%0,%1,%2,%3};"
        : "+f"(d[0]), "+f"(d[1]), "+f"(d[2]), "+f"(d[3])
        : "r"(a0), "r"(a1), "r"(a2), "r"(a3), "r"(b0), "r"(b1));
}

// cumulative pair count before strip si
__device__ __forceinline__ int pair_base(int s) {
    int a = s >> 1;
    return (s & 1) ? (256 * a + 128 - a * a) : (257 * a - a * a);
}

// ---------------- kernel 1: quantize(+permute) + norms + MSE + LUT --------
__global__ void __launch_bounds__(256) prep_fused(const float* __restrict__ E,
                                                  const float* __restrict__ yt,
                                                  const float* __restrict__ yp) {
    const int bid = blockIdx.x, tid = threadIdx.x;
    if (bid < 32) {
        int i = bid * 256 + tid;
        const float4* row = reinterpret_cast<const float4*>(E + (size_t)i * DDIM);
        uint8_t vb[DDIM];
        float s = 0.0f;
#pragma unroll
        for (int qq = 0; qq < 16; qq++) {
            float4 v = row[qq];
            __nv_fp8_e4m3 a0(v.x), a1(v.y), a2(v.z), a3(v.w);
            float f0 = float(a0), f1 = float(a1), f2 = float(a2), f3 = float(a3);
            s += f0 * f0 + f1 * f1 + f2 * f2 + f3 * f3;
            vb[4 * qq + 0] = a0.__x; vb[4 * qq + 1] = a1.__x;
            vb[4 * qq + 2] = a2.__x; vb[4 * qq + 3] = a3.__x;
        }
        // K-permutation: byte pos p = q*16 + t*4 + b  <-  source k = t*16 + q*4 + b
        uint8_t ob[DDIM];
#pragma unroll
        for (int p = 0; p < DDIM; p++) {
            int q = (p >> 4) & 3, t = (p >> 2) & 3, b = p & 3;
            ob[p] = vb[t * 16 + q * 4 + b];
        }
        uint4* dst = reinterpret_cast<uint4*>(g_E8[i]);
        const uint4* src = reinterpret_cast<const uint4*>(ob);
#pragma unroll
        for (int w = 0; w < 4; w++) dst[w] = src[w];
        g_h[i] = -0.5f * s;
        g_rowsum[i] = 0.0f;
    } else if (bid < 32 + MSE_BLOCKS) {
        __shared__ float sh[8];
        int idx = (bid - 32) * 256 + tid;     // over 131072 float4s
        float4 t = reinterpret_cast<const float4*>(yt)[idx];
        float4 p = reinterpret_cast<const float4*>(yp)[idx];
        float dx = p.x - t.x, dy = p.y - t.y, dz = p.z - t.z, dw = p.w - t.w;
        float s = dx * dx + dy * dy + dz * dz + dw * dw;
#pragma unroll
        for (int o = 16; o > 0; o >>= 1) s += __shfl_down_sync(0xffffffffu, s, o);
        if ((tid & 31) == 0) sh[tid >> 5] = s;
        __syncthreads();
        if (tid < 8) {
            s = sh[tid];
#pragma unroll
            for (int o = 4; o > 0; o >>= 1) s += __shfl_down_sync(0xffu, s, o);
            if (tid == 0) g_msep[bid - 32] = s;
        }
    } else {
        int p = (bid - 32 - MSE_BLOCKS) * 256 + tid;
        if (p < NPAIRS2) {
            float disc = 257.0f * 257.0f - 4.0f * (float)p;
            int a = (int)((257.0f - sqrtf(fmaxf(disc, 0.0f))) * 0.5f);
            int si = 2 * a;
            if (si < 0) si = 0;
            if (si > NSTRIP - 1) si = NSTRIP - 1;
            while (si > 0 && pair_base(si) > p) si--;
            while (si + 1 < NSTRIP && pair_base(si + 1) <= p) si++;
            int tj = (si >> 1) + (p - pair_base(si));
            g_pair[p] = (si << 8) | tj;
        }
    }
}

// ---------------- kernel 2: persistent warp-autonomous 32x64 tiles --------
__global__ void __launch_bounds__(256, 2) pair_kernel(float* __restrict__ out) {
    __shared__ unsigned int s_last;
    __shared__ float sh_red[256];

    const int tid  = threadIdx.x;
    const int wid  = tid >> 5;
    const int lane = tid & 31;
    const int g    = lane >> 2;        // 0..7
    const int q    = lane & 3;         // 0..3

    const int gid   = blockIdx.x * 8 + wid;
    const int t_beg = gid * CHUNKW;
    const int t_end = min(t_beg + CHUNKW, NPAIRS2);

    int cur_si = -1;
    uint4 aLo[2], aHi[2];
    float hi[2][2];

    for (int t = t_beg; t < t_end; t++) {
        const int pr = __ldg(&g_pair[t]);
        const int si = pr >> 8, tj = pr & 255;
        const int i0 = si * 32, j0 = tj * 64;
        const bool mirror = (tj != (si >> 1));

        // B fragments + hj: 8 coalesced LDG.128 + 8 LDG.64 (MLP high)
        uint4 bv[8];
        float2 hjv[8];
#pragma unroll
        for (int nt = 0; nt < 8; nt++) {
            bv[nt]  = __ldg(reinterpret_cast<const uint4*>(&g_E8[j0 + nt * 8 + g][q * 16]));
            hjv[nt] = __ldg(reinterpret_cast<const float2*>(&g_h[j0 + nt * 8 + q * 2]));
        }

        if (si != cur_si) {   // rare: strip change within chunk
            cur_si = si;
#pragma unroll
            for (int mt = 0; mt < 2; mt++) {
                aLo[mt] = __ldg(reinterpret_cast<const uint4*>(&g_E8[i0 + mt * 16 + g][q * 16]));
                aHi[mt] = __ldg(reinterpret_cast<const uint4*>(&g_E8[i0 + mt * 16 + g + 8][q * 16]));
                hi[mt][0] = __ldg(&g_h[i0 + mt * 16 + g]);
                hi[mt][1] = __ldg(&g_h[i0 + mt * 16 + g + 8]);
            }
        }

        float acc[2][8][4];
#pragma unroll
        for (int nt = 0; nt < 8; nt++)
#pragma unroll
            for (int mt = 0; mt < 2; mt++) {
                mma_zc(acc[mt][nt], aLo[mt].x, aHi[mt].x, aLo[mt].y, aHi[mt].y,
                       bv[nt].x, bv[nt].y);
                mma_ac(acc[mt][nt], aLo[mt].z, aHi[mt].z, aLo[mt].w, aHi[mt].w,
                       bv[nt].z, bv[nt].w);
            }

        // pruning pass: exact args, warp max, no MUFU
        float wmax = -1e30f;
#pragma unroll
        for (int nt = 0; nt < 8; nt++) {
            float hj0 = hjv[nt].x, hj1 = hjv[nt].y;
#pragma unroll
            for (int mt = 0; mt < 2; mt++) {
                float m0 = fmaxf(acc[mt][nt][0] + (hi[mt][0] + hj0),
                                 acc[mt][nt][1] + (hi[mt][0] + hj1));
                float m1 = fmaxf(acc[mt][nt][2] + (hi[mt][1] + hj0),
                                 acc[mt][nt][3] + (hi[mt][1] + hj1));
                wmax = fmaxf(wmax, fmaxf(m0, m1));
            }
        }

        if (__any_sync(0xffffffffu, wmax > THRESH)) {
            float rs[4] = {0.0f, 0.0f, 0.0f, 0.0f};
            bool rhit = false;
#pragma unroll
            for (int nt = 0; nt < 8; nt++) {
                float hj0 = hjv[nt].x, hj1 = hjv[nt].y;
                // per-nt gate: usually only one nt is hot
                float a00 = acc[0][nt][0] + hi[0][0] + hj0;
                float a01 = acc[0][nt][1] + hi[0][0] + hj1;
                float a02 = acc[0][nt][2] + hi[0][1] + hj0;
                float a03 = acc[0][nt][3] + hi[0][1] + hj1;
                float a10 = acc[1][nt][0] + hi[1][0] + hj0;
                float a11 = acc[1][nt][1] + hi[1][0] + hj1;
                float a12 = acc[1][nt][2] + hi[1][1] + hj0;
                float a13 = acc[1][nt][3] + hi[1][1] + hj1;
                float nmax = fmaxf(fmaxf(fmaxf(a00, a01), fmaxf(a02, a03)),
                                   fmaxf(fmaxf(a10, a11), fmaxf(a12, a13)));
                if (__any_sync(0xffffffffu, nmax > THRESH)) {
                    rhit = true;
                    float e00 = __expf(fminf(a00, 0.0f));
                    float e01 = __expf(fminf(a01, 0.0f));
                    float e02 = __expf(fminf(a02, 0.0f));
                    float e03 = __expf(fminf(a03, 0.0f));
                    float e10 = __expf(fminf(a10, 0.0f));
                    float e11 = __expf(fminf(a11, 0.0f));
                    float e12 = __expf(fminf(a12, 0.0f));
                    float e13 = __expf(fminf(a13, 0.0f));
                    rs[0] += e00 + e01;
                    rs[1] += e02 + e03;
                    rs[2] += e10 + e11;
                    rs[3] += e12 + e13;
                    if (mirror) {
                        float c0 = e00 + e02 + e10 + e12;
                        float c1 = e01 + e03 + e11 + e13;
                        c0 += __shfl_xor_sync(0xffffffffu, c0, 4);
                        c0 += __shfl_xor_sync(0xffffffffu, c0, 8);
                        c0 += __shfl_xor_sync(0xffffffffu, c0, 16);
                        c1 += __shfl_xor_sync(0xffffffffu, c1, 4);
                        c1 += __shfl_xor_sync(0xffffffffu, c1, 8);
                        c1 += __shfl_xor_sync(0xffffffffu, c1, 16);
                        if (g == nt) {
                            atomicAdd(&g_rowsum[j0 + nt * 8 + q * 2], c0);
                            atomicAdd(&g_rowsum[j0 + nt * 8 + q * 2 + 1], c1);
                        }
                    }
                }
            }
            if (rhit) {
#pragma unroll
                for (int k = 0; k < 4; k++) {
                    rs[k] += __shfl_xor_sync(0xffffffffu, rs[k], 1);
                    rs[k] += __shfl_xor_sync(0xffffffffu, rs[k], 2);
                }
                int row = i0 + (q >> 1) * 16 + (q & 1) * 8 + g;
                atomicAdd(&g_rowsum[row], rs[q]);
            }
        }
    }

    // ---- last-CTA final reduction ----
    __threadfence();
    __syncthreads();
    if (tid == 0) {
        unsigned int old = atomicAdd(&g_ctr, 1u);
        s_last = (old == gridDim.x - 1) ? 1u : 0u;
        if (s_last) g_ctr = 0;   // reset for next graph replay
    }
    __syncthreads();
    if (s_last) {
        float s = 0.0f;
        for (int i = tid; i < NROWS; i += 256) s += logf(__ldcg(&g_rowsum[i]));
        float m = 0.0f;
        for (int i = tid; i < MSE_BLOCKS; i += 256) m += g_msep[i];
        sh_red[tid] = s;
        __syncthreads();
        for (int o = 128; o > 0; o >>= 1) {
            if (tid < o) sh_red[tid] += sh_red[tid + o];
            __syncthreads();
        }
        float stot = sh_red[0];
        __syncthreads();
        sh_red[tid] = m;
        __syncthreads();
        for (int o = 128; o > 0; o >>= 1) {
            if (tid < o) sh_red[tid] += sh_red[tid + o];
            __syncthreads();
        }
        if (tid == 0) {
            float kde  = stot / (float)NROWS;
            float IXT  = (logf((float)NROWS) - kde) * 1.44269504088896340736f;
            float dist = sh_red[0] / (float)(NROWS * DDIM);
            out[0] = IXT + 500.0f * dist;
            out[1] = IXT;
            out[2] = dist;
        }
    }
}

extern "C" void kernel_launch(void* const* d_in, const int* in_sizes, int n_in,
                              void* d_out, int out_size) {
    const float* y_true  = (const float*)d_in[0];
    const float* y_pred  = (const float*)d_in[1];
    const float* encoded = (const float*)d_in[2];
    float* out = (float*)d_out;

    prep_fused<<<32 + MSE_BLOCKS + LUT_BLOCKS, 256>>>(encoded, y_true, y_pred);
    pair_kernel<<<GRID, 256>>>(out);
}